// round 1
// baseline (speedup 1.0000x reference)
#include <cuda_runtime.h>
#include <cuda_bf16.h>

// Problem constants: b=2, h=16, L=4096, d=128, chunk=32
#define NTILES   4096            // b*h*(L/chunk) = 2*16*128
#define OUT_ELEMS 16777216       // 2*16*4096*128
#define S_ELEMS   524288         // 2*16*128*128

// Scratch (static device globals -- no allocation at runtime)
__device__ float g_qn[16777216];
__device__ float g_kn[16777216];
__device__ float g_w [16777216];
__device__ float g_u [16777216];
__device__ float g_attn[4194304];

// 32x32 matmul on shared buffers: out = (adds? adds:0) + a @ b
// 256 threads: thread -> (i = tid>>3, 4 cols j4..j4+3)
__device__ __forceinline__ void mm32(float* __restrict__ out,
                                     const float* __restrict__ a,
                                     const float* __restrict__ b,
                                     const float* __restrict__ adds,
                                     int tid) {
    int i  = tid >> 3;
    int j4 = (tid & 7) << 2;
    float ar[32];
#pragma unroll
    for (int c = 0; c < 8; c++) {
        float4 t = *(const float4*)(a + i * 32 + c * 4);
        ar[c*4+0] = t.x; ar[c*4+1] = t.y; ar[c*4+2] = t.z; ar[c*4+3] = t.w;
    }
    float4 acc;
    if (adds) acc = *(const float4*)(adds + i * 32 + j4);
    else      acc = make_float4(0.f, 0.f, 0.f, 0.f);
#pragma unroll
    for (int kk = 0; kk < 32; kk++) {
        float4 bb = *(const float4*)(b + kk * 32 + j4);
        acc.x = fmaf(ar[kk], bb.x, acc.x);
        acc.y = fmaf(ar[kk], bb.y, acc.y);
        acc.z = fmaf(ar[kk], bb.z, acc.z);
        acc.w = fmaf(ar[kk], bb.w, acc.w);
    }
    *(float4*)(out + i * 32 + j4) = acc;
}

// ---------------------------------------------------------------------------
// Kernel 1: per chunk-tile (4096 CTAs). Normalize q,k; build T0; invert;
// emit qn, kn, w = inv@(k*beta), u = inv@(v*beta), attn = tril(qn kn^T).
// ---------------------------------------------------------------------------
extern __shared__ float sm1[];

__global__ void __launch_bounds__(256, 2)
k1_kernel(const float* __restrict__ q, const float* __restrict__ k,
          const float* __restrict__ v, const float* __restrict__ beta) {
    float* qn = sm1;            // 4096
    float* kn = sm1 + 4096;     // 4096
    float* vb = sm1 + 8192;     // 4096
    float* Am = sm1 + 12288;    // 1024
    float* Bm = sm1 + 13312;    // 1024
    float* Xm = sm1 + 14336;    // 1024
    float* Ym = sm1 + 15360;    // 1024
    float* beta_s = sm1 + 16384;// 32

    const int tid  = threadIdx.x;
    const int tile = blockIdx.x;
    const size_t base = (size_t)tile * 4096;   // element offset into q/k/v
    const int brow = tile * 32;                // offset into beta

    // ---- load + l2norm q,k (8 warps x 4 rows; one warp covers a 128-row) ----
    {
        int wp = tid >> 5, lane = tid & 31;
#pragma unroll
        for (int rr = 0; rr < 4; rr++) {
            int r = wp * 4 + rr;
            // q row
            float4 a = *(const float4*)(q + base + r * 128 + lane * 4);
            float s = a.x*a.x + a.y*a.y + a.z*a.z + a.w*a.w;
#pragma unroll
            for (int off = 16; off; off >>= 1) s += __shfl_xor_sync(0xffffffffu, s, off);
            float sc = rsqrtf(s + 1e-6f);
            float4 o = make_float4(a.x*sc, a.y*sc, a.z*sc, a.w*sc);
            *(float4*)(qn + r * 128 + lane * 4) = o;
            *(float4*)(g_qn + base + r * 128 + lane * 4) = o;
            // k row
            float4 b = *(const float4*)(k + base + r * 128 + lane * 4);
            float sk = b.x*b.x + b.y*b.y + b.z*b.z + b.w*b.w;
#pragma unroll
            for (int off = 16; off; off >>= 1) sk += __shfl_xor_sync(0xffffffffu, sk, off);
            float sck = rsqrtf(sk + 1e-6f);
            float4 ok = make_float4(b.x*sck, b.y*sck, b.z*sck, b.w*sck);
            *(float4*)(kn + r * 128 + lane * 4) = ok;
            *(float4*)(g_kn + base + r * 128 + lane * 4) = ok;
        }
        if (tid < 32) beta_s[tid] = beta[brow + tid];
    }
    __syncthreads();

    // ---- vb = v * beta ----
    for (int x = tid; x < 1024; x += 256) {
        int r = x >> 5, c4 = (x & 31) << 2;
        float4 vv = *(const float4*)(v + base + r * 128 + c4);
        float bb = beta_s[r];
        *(float4*)(vb + r * 128 + c4) = make_float4(vv.x*bb, vv.y*bb, vv.z*bb, vv.w*bb);
    }

    // ---- T0 = strict_lower(-(k*beta) @ kn^T); attn = tril(qn @ kn^T) ----
    for (int x = tid; x < 1024; x += 256) {
        int i = x >> 5, j = x & 31;
        const float4* ki = (const float4*)(kn + i * 128);
        const float4* kj = (const float4*)(kn + j * 128);
        const float4* qi = (const float4*)(qn + i * 128);
        float aK = 0.f, aQ = 0.f;
#pragma unroll
        for (int c = 0; c < 32; c++) {
            float4 bj = kj[c];
            float4 ai = ki[c];
            float4 qq = qi[c];
            aK = fmaf(ai.x, bj.x, fmaf(ai.y, bj.y, fmaf(ai.z, bj.z, fmaf(ai.w, bj.w, aK))));
            aQ = fmaf(qq.x, bj.x, fmaf(qq.y, bj.y, fmaf(qq.z, bj.z, fmaf(qq.w, bj.w, aQ))));
        }
        float t0 = (i > j) ? (-beta_s[i] * aK) : 0.f;
        Am[x] = t0;
        Xm[x] = t0 + ((i == j) ? 1.f : 0.f);            // X = I + A
        g_attn[(size_t)tile * 1024 + x] = (i >= j) ? aQ : 0.f;
    }

    // ---- (I - T0)^{-1} = (I+A)(I+A^2)(I+A^4)(I+A^8)(I+A^16), A nilpotent ----
    float *Ap = Am, *Bp = Bm, *Xp = Xm, *Yp = Ym;
#pragma unroll 1
    for (int s = 0; s < 4; s++) {
        __syncthreads();
        mm32(Bp, Ap, Ap, nullptr, tid);   // B = A @ A
        __syncthreads();
        mm32(Yp, Xp, Bp, Xp, tid);        // Y = X + X @ B
        float* t;
        t = Ap; Ap = Bp; Bp = t;
        t = Xp; Xp = Yp; Yp = t;
    }
    __syncthreads();
    // Xp = (I - T0)^{-1}

    // ---- w = Xp @ (kn * beta_col), u = Xp @ vb  (32x128 each) ----
    {
        int i  = tid >> 3;
        int jg = tid & 7;
        float xr[32], xb[32];
#pragma unroll
        for (int c = 0; c < 8; c++) {
            float4 t = *(const float4*)(Xp + i * 32 + c * 4);
            xr[c*4+0] = t.x; xr[c*4+1] = t.y; xr[c*4+2] = t.z; xr[c*4+3] = t.w;
        }
#pragma unroll
        for (int kk = 0; kk < 32; kk++) xb[kk] = xr[kk] * beta_s[kk];

#pragma unroll 1
        for (int cblk = 0; cblk < 4; cblk++) {
            int c = cblk * 32 + jg * 4;
            float4 aw = make_float4(0.f, 0.f, 0.f, 0.f);
            float4 au = make_float4(0.f, 0.f, 0.f, 0.f);
#pragma unroll
            for (int kk = 0; kk < 32; kk++) {
                float4 kv = *(const float4*)(kn + kk * 128 + c);
                float4 vv = *(const float4*)(vb + kk * 128 + c);
                aw.x = fmaf(xb[kk], kv.x, aw.x); aw.y = fmaf(xb[kk], kv.y, aw.y);
                aw.z = fmaf(xb[kk], kv.z, aw.z); aw.w = fmaf(xb[kk], kv.w, aw.w);
                au.x = fmaf(xr[kk], vv.x, au.x); au.y = fmaf(xr[kk], vv.y, au.y);
                au.z = fmaf(xr[kk], vv.z, au.z); au.w = fmaf(xr[kk], vv.w, au.w);
            }
            *(float4*)(g_w + base + i * 128 + c) = aw;
            *(float4*)(g_u + base + i * 128 + c) = au;
        }
    }
}

// ---------------------------------------------------------------------------
// Kernel 2: sequential scan. Grid (4 dv-slices, 16 h, 2 b). S kept in shared.
//   ui = u0 - w @ S ; o = q @ S + attn @ ui ; S += kn^T @ ui
// ---------------------------------------------------------------------------
extern __shared__ float sm2[];

__global__ void __launch_bounds__(256, 1)
k2_kernel(float* __restrict__ out, int out_size) {
    float* S    = sm2;           // 4096  (128 dk x 32 dv-slice)
    float* wsh  = sm2 + 4096;    // 4096
    float* qsh  = sm2 + 8192;    // 4096
    float* ksh  = sm2 + 12288;   // 4096
    float* ush  = sm2 + 16384;   // 1024
    float* ash  = sm2 + 17408;   // 1024
    float* uish = sm2 + 18432;   // 1024

    const int tid = threadIdx.x;
    const int sl  = blockIdx.x;                    // dv slice 0..3
    const int bh  = blockIdx.z * 16 + blockIdx.y;  // 0..31
    const int i   = tid >> 3;
    const int j4  = (tid & 7) << 2;

    for (int x = tid; x < 4096; x += 256) S[x] = 0.f;
    __syncthreads();

#pragma unroll 1
    for (int n = 0; n < 128; n++) {
        const size_t tb = ((size_t)bh * 128 + n) * 4096;
        // stage this chunk's tensors into shared
        {
            const float4* gw = (const float4*)(g_w  + tb);
            const float4* gq = (const float4*)(g_qn + tb);
            const float4* gk = (const float4*)(g_kn + tb);
            float4* sw = (float4*)wsh; float4* sq = (float4*)qsh; float4* sk = (float4*)ksh;
            for (int x = tid; x < 1024; x += 256) {
                sw[x] = gw[x]; sq[x] = gq[x]; sk[x] = gk[x];
            }
            // u0 slice (32 x 32): one float4 per thread
            *(float4*)(ush + i * 32 + j4) =
                *(const float4*)(g_u + tb + i * 128 + sl * 32 + j4);
            // attn (32 x 32): one float4 per thread
            *(float4*)(ash + tid * 4) =
                *(const float4*)(g_attn + ((size_t)bh * 128 + n) * 1024 + tid * 4);
        }
        __syncthreads();

        // ui = u0 - w @ S
        {
            float4 acc = *(const float4*)(ush + i * 32 + j4);
#pragma unroll 8
            for (int kk = 0; kk < 128; kk++) {
                float a = wsh[i * 128 + kk];
                float4 b = *(const float4*)(S + kk * 32 + j4);
                acc.x = fmaf(-a, b.x, acc.x);
                acc.y = fmaf(-a, b.y, acc.y);
                acc.z = fmaf(-a, b.z, acc.z);
                acc.w = fmaf(-a, b.w, acc.w);
            }
            *(float4*)(uish + i * 32 + j4) = acc;
        }
        __syncthreads();

        // o = q @ S + attn @ ui ; write straight to gmem
        {
            float4 o4 = make_float4(0.f, 0.f, 0.f, 0.f);
#pragma unroll 8
            for (int kk = 0; kk < 128; kk++) {
                float a = qsh[i * 128 + kk];
                float4 b = *(const float4*)(S + kk * 32 + j4);
                o4.x = fmaf(a, b.x, o4.x); o4.y = fmaf(a, b.y, o4.y);
                o4.z = fmaf(a, b.z, o4.z); o4.w = fmaf(a, b.w, o4.w);
            }
#pragma unroll 8
            for (int c = 0; c < 32; c++) {
                float a = ash[i * 32 + c];
                float4 b = *(const float4*)(uish + c * 32 + j4);
                o4.x = fmaf(a, b.x, o4.x); o4.y = fmaf(a, b.y, o4.y);
                o4.z = fmaf(a, b.z, o4.z); o4.w = fmaf(a, b.w, o4.w);
            }
            *(float4*)(out + ((size_t)bh * 4096 + n * 32 + i) * 128 + sl * 32 + j4) = o4;
        }
        __syncthreads();   // everyone done reading S before updating it

        // S += kn^T @ ui   (128 x 32 <- 128x32-of-kn^T times 32x32)
        {
#pragma unroll 1
            for (int kb = 0; kb < 4; kb++) {
                int kd = kb * 32 + i;
                float4 s4 = *(const float4*)(S + kd * 32 + j4);
#pragma unroll 8
                for (int c = 0; c < 32; c++) {
                    float a = ksh[c * 128 + kd];
                    float4 b = *(const float4*)(uish + c * 32 + j4);
                    s4.x = fmaf(a, b.x, s4.x); s4.y = fmaf(a, b.y, s4.y);
                    s4.z = fmaf(a, b.z, s4.z); s4.w = fmaf(a, b.w, s4.w);
                }
                *(float4*)(S + kd * 32 + j4) = s4;
            }
        }
        // next iteration's first __syncthreads orders these writes
    }
    __syncthreads();

    // final state S -> second output tensor (b,h,dk,dv)
    if (out_size >= OUT_ELEMS + S_ELEMS) {
#pragma unroll 1
        for (int kb = 0; kb < 4; kb++) {
            int kd = kb * 32 + i;
            *(float4*)(out + OUT_ELEMS + ((size_t)bh * 128 + kd) * 128 + sl * 32 + j4) =
                *(const float4*)(S + kd * 32 + j4);
        }
    }
}

// ---------------------------------------------------------------------------
extern "C" void kernel_launch(void* const* d_in, const int* in_sizes, int n_in,
                              void* d_out, int out_size) {
    const float* q    = (const float*)d_in[0];
    const float* k    = (const float*)d_in[1];
    const float* v    = (const float*)d_in[2];
    const float* beta = (const float*)d_in[3];
    float* out = (float*)d_out;

    static bool attr_done = false;
    // setting func attributes is idempotent and not a stream op; safe to repeat
    cudaFuncSetAttribute(k1_kernel, cudaFuncAttributeMaxDynamicSharedMemorySize, 16416 * 4);
    cudaFuncSetAttribute(k2_kernel, cudaFuncAttributeMaxDynamicSharedMemorySize, 19456 * 4);
    (void)attr_done;

    k1_kernel<<<NTILES, 256, 16416 * 4>>>(q, k, v, beta);
    k2_kernel<<<dim3(4, 16, 2), 256, 19456 * 4>>>(out, out_size);
}

// round 2
// speedup vs baseline: 1.9663x; 1.9663x over previous
#include <cuda_runtime.h>
#include <cuda_bf16.h>
#include <cstdint>

// Problem constants: b=2, h=16, L=4096, d=128, chunk=32
#define NTILES   4096            // b*h*(L/chunk)
#define OUT_ELEMS 16777216       // 2*16*4096*128
#define S_ELEMS   524288         // 2*16*128*128

#define PW 132                   // padded stride for 128-wide rows
#define PS 36                    // padded stride for 32-wide rows

// Scratch (static device globals -- no allocation at runtime)
__device__ float g_qn[16777216];
__device__ float g_kn[16777216];
__device__ float g_w [16777216];
__device__ float g_u [16777216];
__device__ float g_attn[4194304];

__device__ __forceinline__ void cpa16(float* dst_smem, const float* src_gmem) {
    uint32_t d = (uint32_t)__cvta_generic_to_shared(dst_smem);
    asm volatile("cp.async.cg.shared.global [%0], [%1], 16;\n" :: "r"(d), "l"(src_gmem));
}
#define CP_COMMIT() asm volatile("cp.async.commit_group;\n" ::: "memory")
#define CP_WAIT0()  asm volatile("cp.async.wait_group 0;\n" ::: "memory")

// 32x32 matmul on shared (stride-32 mats): out = (adds? adds:0) + a @ b
__device__ __forceinline__ void mm32(float* __restrict__ out,
                                     const float* __restrict__ a,
                                     const float* __restrict__ b,
                                     const float* __restrict__ adds,
                                     int tid) {
    int i  = tid >> 3;
    int j4 = (tid & 7) << 2;
    float ar[32];
#pragma unroll
    for (int c = 0; c < 8; c++) {
        float4 t = *(const float4*)(a + i * 32 + c * 4);
        ar[c*4+0] = t.x; ar[c*4+1] = t.y; ar[c*4+2] = t.z; ar[c*4+3] = t.w;
    }
    float4 acc;
    if (adds) acc = *(const float4*)(adds + i * 32 + j4);
    else      acc = make_float4(0.f, 0.f, 0.f, 0.f);
#pragma unroll
    for (int kk = 0; kk < 32; kk++) {
        float4 bb = *(const float4*)(b + kk * 32 + j4);
        acc.x = fmaf(ar[kk], bb.x, acc.x);
        acc.y = fmaf(ar[kk], bb.y, acc.y);
        acc.z = fmaf(ar[kk], bb.z, acc.z);
        acc.w = fmaf(ar[kk], bb.w, acc.w);
    }
    *(float4*)(out + i * 32 + j4) = acc;
}

// ---------------------------------------------------------------------------
// Kernel 1: per chunk-tile (4096 CTAs).
// ---------------------------------------------------------------------------
extern __shared__ float sm1[];

__global__ void __launch_bounds__(256, 3)
k1_kernel(const float* __restrict__ q, const float* __restrict__ k,
          const float* __restrict__ v, const float* __restrict__ beta) {
    float* qn = sm1;                 // 32*132
    float* kn = qn + 32 * PW;        // 32*132
    float* vb = kn + 32 * PW;        // 32*132
    float* Am = vb + 32 * PW;        // 1024
    float* Bm = Am + 1024;
    float* Xm = Bm + 1024;
    float* Ym = Xm + 1024;
    float* beta_s = Ym + 1024;       // 32

    const int tid  = threadIdx.x;
    const int tile = blockIdx.x;
    const size_t base = (size_t)tile * 4096;
    const int brow = tile * 32;

    // ---- load + l2norm q,k (8 warps x 4 rows) ----
    {
        int wp = tid >> 5, lane = tid & 31;
#pragma unroll
        for (int rr = 0; rr < 4; rr++) {
            int r = wp * 4 + rr;
            float4 a = *(const float4*)(q + base + r * 128 + lane * 4);
            float s = a.x*a.x + a.y*a.y + a.z*a.z + a.w*a.w;
#pragma unroll
            for (int off = 16; off; off >>= 1) s += __shfl_xor_sync(0xffffffffu, s, off);
            float sc = rsqrtf(s + 1e-6f);
            float4 o = make_float4(a.x*sc, a.y*sc, a.z*sc, a.w*sc);
            *(float4*)(qn + r * PW + lane * 4) = o;
            *(float4*)(g_qn + base + r * 128 + lane * 4) = o;

            float4 b = *(const float4*)(k + base + r * 128 + lane * 4);
            float sk = b.x*b.x + b.y*b.y + b.z*b.z + b.w*b.w;
#pragma unroll
            for (int off = 16; off; off >>= 1) sk += __shfl_xor_sync(0xffffffffu, sk, off);
            float sck = rsqrtf(sk + 1e-6f);
            float4 ok = make_float4(b.x*sck, b.y*sck, b.z*sck, b.w*sck);
            *(float4*)(kn + r * PW + lane * 4) = ok;
            *(float4*)(g_kn + base + r * 128 + lane * 4) = ok;
        }
        if (tid < 32) beta_s[tid] = beta[brow + tid];
    }
    __syncthreads();

    // ---- vb = v * beta ----
    for (int x = tid; x < 1024; x += 256) {
        int r = x >> 5, c4 = (x & 31) << 2;
        float4 vv = *(const float4*)(v + base + r * 128 + c4);
        float bb = beta_s[r];
        *(float4*)(vb + r * PW + c4) = make_float4(vv.x*bb, vv.y*bb, vv.z*bb, vv.w*bb);
    }
    __syncthreads();

    // ---- T0 = strict_lower(-(k*beta) @ kn^T); attn = tril(qn kn^T) ----
    // warp = fixed j (lane); each thread handles 4 i-rows (iw + 8*s).
    {
        const int j  = tid & 31;
        const int iw = tid >> 5;
        float accK[4] = {0.f,0.f,0.f,0.f};
        float accQ[4] = {0.f,0.f,0.f,0.f};
#pragma unroll 4
        for (int c4 = 0; c4 < 32; c4++) {
            float4 kj = *(const float4*)(kn + j * PW + c4 * 4);
#pragma unroll
            for (int s = 0; s < 4; s++) {
                int ir = iw + 8 * s;
                float4 ki = *(const float4*)(kn + ir * PW + c4 * 4);
                float4 qi = *(const float4*)(qn + ir * PW + c4 * 4);
                accK[s] = fmaf(ki.x, kj.x, fmaf(ki.y, kj.y, fmaf(ki.z, kj.z, fmaf(ki.w, kj.w, accK[s]))));
                accQ[s] = fmaf(qi.x, kj.x, fmaf(qi.y, kj.y, fmaf(qi.z, kj.z, fmaf(qi.w, kj.w, accQ[s]))));
            }
        }
#pragma unroll
        for (int s = 0; s < 4; s++) {
            int ir = iw + 8 * s;
            int x = ir * 32 + j;
            float t0 = (ir > j) ? (-beta_s[ir] * accK[s]) : 0.f;
            Am[x] = t0;
            Xm[x] = t0 + ((ir == j) ? 1.f : 0.f);
            g_attn[(size_t)tile * 1024 + x] = (ir >= j) ? accQ[s] : 0.f;
        }
    }

    // ---- (I - T0)^{-1} via nilpotent squaring ----
    float *Ap = Am, *Bp = Bm, *Xp = Xm, *Yp = Ym;
#pragma unroll 1
    for (int s = 0; s < 4; s++) {
        __syncthreads();
        mm32(Bp, Ap, Ap, nullptr, tid);
        __syncthreads();
        mm32(Yp, Xp, Bp, Xp, tid);
        float* t;
        t = Ap; Ap = Bp; Bp = t;
        t = Xp; Xp = Yp; Yp = t;
    }
    __syncthreads();

    // ---- w = Xp @ (kn * beta_col), u = Xp @ vb ----
    {
        int i  = tid >> 3;
        int jg = tid & 7;
        float xr[32], xb[32];
#pragma unroll
        for (int c = 0; c < 8; c++) {
            float4 t = *(const float4*)(Xp + i * 32 + c * 4);
            xr[c*4+0] = t.x; xr[c*4+1] = t.y; xr[c*4+2] = t.z; xr[c*4+3] = t.w;
        }
#pragma unroll
        for (int kk = 0; kk < 32; kk++) xb[kk] = xr[kk] * beta_s[kk];

#pragma unroll 1
        for (int cblk = 0; cblk < 4; cblk++) {
            int c = cblk * 32 + jg * 4;
            float4 aw = make_float4(0.f, 0.f, 0.f, 0.f);
            float4 au = make_float4(0.f, 0.f, 0.f, 0.f);
#pragma unroll
            for (int kk = 0; kk < 32; kk++) {
                float4 kv = *(const float4*)(kn + kk * PW + c);
                float4 vv = *(const float4*)(vb + kk * PW + c);
                aw.x = fmaf(xb[kk], kv.x, aw.x); aw.y = fmaf(xb[kk], kv.y, aw.y);
                aw.z = fmaf(xb[kk], kv.z, aw.z); aw.w = fmaf(xb[kk], kv.w, aw.w);
                au.x = fmaf(xr[kk], vv.x, au.x); au.y = fmaf(xr[kk], vv.y, au.y);
                au.z = fmaf(xr[kk], vv.z, au.z); au.w = fmaf(xr[kk], vv.w, au.w);
            }
            *(float4*)(g_w + base + i * 128 + c) = aw;
            *(float4*)(g_u + base + i * 128 + c) = au;
        }
    }
}

// ---------------------------------------------------------------------------
// Kernel 2: sequential scan, 128 CTAs (4 dv-slices x 32 bh), cp.async
// double-buffered staging, fused ui/o K-loop, loop-swapped S update.
// ---------------------------------------------------------------------------
#define BUF_FLOATS (3 * 32 * PW + 2 * 32 * PS)   // w,q,k (32x132) + u,a (32x36) = 14976

extern __shared__ float sm2[];

__device__ __forceinline__ void k2_prefetch(int n, float* buf, int bh, int sl, int tid) {
    const size_t tb = ((size_t)bh * 128 + n) * 4096;
    float* w = buf;
    float* q = buf + 32 * PW;
    float* k = buf + 64 * PW;
    float* u = buf + 96 * PW;
    float* a = buf + 96 * PW + 32 * PS;
#pragma unroll
    for (int t = 0; t < 4; t++) {
        int idx = tid + t * 256;           // 0..1023 float4 positions
        int r = idx >> 5, c4 = (idx & 31) << 2;
        cpa16(w + r * PW + c4, g_w  + tb + r * 128 + c4);
        cpa16(q + r * PW + c4, g_qn + tb + r * 128 + c4);
        cpa16(k + r * PW + c4, g_kn + tb + r * 128 + c4);
    }
    {
        int r = tid >> 3, c4 = (tid & 7) << 2;
        cpa16(u + r * PS + c4, g_u + tb + r * 128 + sl * 32 + c4);
        cpa16(a + r * PS + c4, g_attn + ((size_t)bh * 128 + n) * 1024 + r * 32 + c4);
    }
}

__global__ void __launch_bounds__(256, 1)
k2_kernel(float* __restrict__ out, int out_size) {
    float* S    = sm2;                        // 128*36 = 4608
    float* uish = S + 128 * PS;               // 32*36  = 1152
    float* bufs = uish + 32 * PS;             // 2 * BUF_FLOATS

    const int tid = threadIdx.x;
    const int sl  = blockIdx.x;
    const int bh  = blockIdx.z * 16 + blockIdx.y;
    const int i   = tid >> 3;
    const int j4  = (tid & 7) << 2;

    for (int x = tid; x < 128 * PS; x += 256) S[x] = 0.f;

    k2_prefetch(0, bufs, bh, sl, tid);
    CP_COMMIT();

#pragma unroll 1
    for (int n = 0; n < 128; n++) {
        float* buf = bufs + (n & 1) * BUF_FLOATS;
        CP_WAIT0();
        __syncthreads();
        if (n + 1 < 128) { k2_prefetch(n + 1, bufs + ((n + 1) & 1) * BUF_FLOATS, bh, sl, tid); CP_COMMIT(); }

        const float* w = buf;
        const float* q = buf + 32 * PW;
        const float* k = buf + 64 * PW;
        const float* u = buf + 96 * PW;
        const float* a = buf + 96 * PW + 32 * PS;

        // fused: aui = u0 - w@S ; ao = q@S
        float4 aui = *(const float4*)(u + i * PS + j4);
        float4 ao  = make_float4(0.f, 0.f, 0.f, 0.f);
#pragma unroll 4
        for (int kk = 0; kk < 128; kk++) {
            float wv = w[i * PW + kk];
            float qv = q[i * PW + kk];
            float4 s = *(const float4*)(S + kk * PS + j4);
            aui.x = fmaf(-wv, s.x, aui.x); aui.y = fmaf(-wv, s.y, aui.y);
            aui.z = fmaf(-wv, s.z, aui.z); aui.w = fmaf(-wv, s.w, aui.w);
            ao.x  = fmaf( qv, s.x, ao.x);  ao.y  = fmaf( qv, s.y, ao.y);
            ao.z  = fmaf( qv, s.z, ao.z);  ao.w  = fmaf( qv, s.w, ao.w);
        }
        *(float4*)(uish + i * PS + j4) = aui;
        __syncthreads();

        // o = ao + attn @ ui
#pragma unroll 4
        for (int c = 0; c < 32; c++) {
            float av = a[i * PS + c];
            float4 uu = *(const float4*)(uish + c * PS + j4);
            ao.x = fmaf(av, uu.x, ao.x); ao.y = fmaf(av, uu.y, ao.y);
            ao.z = fmaf(av, uu.z, ao.z); ao.w = fmaf(av, uu.w, ao.w);
        }
        *(float4*)(out + ((size_t)bh * 4096 + n * 32 + i) * 128 + sl * 32 + j4) = ao;

        // S += kn^T @ ui  (loop-swapped: c outer, 16 accumulators)
        float4 s0 = *(const float4*)(S + (i      ) * PS + j4);
        float4 s1 = *(const float4*)(S + (i + 32 ) * PS + j4);
        float4 s2 = *(const float4*)(S + (i + 64 ) * PS + j4);
        float4 s3 = *(const float4*)(S + (i + 96 ) * PS + j4);
#pragma unroll 4
        for (int c = 0; c < 32; c++) {
            float4 uu = *(const float4*)(uish + c * PS + j4);
            float k0 = k[c * PW + i];
            float k1 = k[c * PW + 32 + i];
            float k2 = k[c * PW + 64 + i];
            float k3 = k[c * PW + 96 + i];
            s0.x = fmaf(k0, uu.x, s0.x); s0.y = fmaf(k0, uu.y, s0.y);
            s0.z = fmaf(k0, uu.z, s0.z); s0.w = fmaf(k0, uu.w, s0.w);
            s1.x = fmaf(k1, uu.x, s1.x); s1.y = fmaf(k1, uu.y, s1.y);
            s1.z = fmaf(k1, uu.z, s1.z); s1.w = fmaf(k1, uu.w, s1.w);
            s2.x = fmaf(k2, uu.x, s2.x); s2.y = fmaf(k2, uu.y, s2.y);
            s2.z = fmaf(k2, uu.z, s2.z); s2.w = fmaf(k2, uu.w, s2.w);
            s3.x = fmaf(k3, uu.x, s3.x); s3.y = fmaf(k3, uu.y, s3.y);
            s3.z = fmaf(k3, uu.z, s3.z); s3.w = fmaf(k3, uu.w, s3.w);
        }
        *(float4*)(S + (i      ) * PS + j4) = s0;
        *(float4*)(S + (i + 32 ) * PS + j4) = s1;
        *(float4*)(S + (i + 64 ) * PS + j4) = s2;
        *(float4*)(S + (i + 96 ) * PS + j4) = s3;
    }
    __syncthreads();

    // final state S -> second output tensor (b,h,dk,dv)
    if (out_size >= OUT_ELEMS + S_ELEMS) {
#pragma unroll
        for (int kb = 0; kb < 4; kb++) {
            int kd = kb * 32 + i;
            *(float4*)(out + OUT_ELEMS + ((size_t)bh * 128 + kd) * 128 + sl * 32 + j4) =
                *(const float4*)(S + kd * PS + j4);
        }
    }
}

// ---------------------------------------------------------------------------
extern "C" void kernel_launch(void* const* d_in, const int* in_sizes, int n_in,
                              void* d_out, int out_size) {
    const float* q    = (const float*)d_in[0];
    const float* k    = (const float*)d_in[1];
    const float* v    = (const float*)d_in[2];
    const float* beta = (const float*)d_in[3];
    float* out = (float*)d_out;

    const int k1_smem = (3 * 32 * PW + 4 * 1024 + 32) * 4;            // 67,328 B
    const int k2_smem = (128 * PS + 32 * PS + 2 * BUF_FLOATS) * 4;    // 142,848 B

    cudaFuncSetAttribute(k1_kernel, cudaFuncAttributeMaxDynamicSharedMemorySize, k1_smem);
    cudaFuncSetAttribute(k2_kernel, cudaFuncAttributeMaxDynamicSharedMemorySize, k2_smem);

    k1_kernel<<<NTILES, 256, k1_smem>>>(q, k, v, beta);
    k2_kernel<<<dim3(4, 16, 2), 256, k2_smem>>>(out, out_size);
}

// round 3
// speedup vs baseline: 2.0600x; 1.0476x over previous
#include <cuda_runtime.h>
#include <cstdint>

// Problem constants: b=2, h=16, L=4096, d=128, chunk=32
#define NTILES   4096
#define OUT_ELEMS 16777216
#define S_ELEMS   524288
#define PW 132                   // padded stride for 128-wide rows
#define PS 36                    // padded stride for 32-wide rows

typedef unsigned long long u64;

// Scratch (static device globals). g_w holds NEGATED w.
__device__ float g_qn[16777216];
__device__ float g_kn[16777216];
__device__ float g_w [16777216];
__device__ float g_u [16777216];
__device__ float g_attn[4194304];

#define FMA2(d, a, b, c) asm("fma.rn.f32x2 %0, %1, %2, %3;" : "=l"(d) : "l"(a), "l"(b), "l"(c))
#define ADD2(d, a, b)    asm("add.rn.f32x2 %0, %1, %2;"     : "=l"(d) : "l"(a), "l"(b))
#define PK2(d, lo, hi)   asm("mov.b64 %0, {%1, %2};"        : "=l"(d) : "f"(lo), "f"(hi))
#define UPK2(lo, hi, s)  asm("mov.b64 {%0, %1}, %2;"        : "=f"(lo), "=f"(hi) : "l"(s))

__device__ __forceinline__ void cpa16(float* dst_smem, const float* src_gmem) {
    uint32_t d = (uint32_t)__cvta_generic_to_shared(dst_smem);
    asm volatile("cp.async.cg.shared.global [%0], [%1], 16;\n" :: "r"(d), "l"(src_gmem));
}
#define CP_COMMIT() asm volatile("cp.async.commit_group;\n" ::: "memory")
#define CP_WAIT0()  asm volatile("cp.async.wait_group 0;\n" ::: "memory")

// 32x32 matmul on shared (stride-32): out = (adds? adds:0) + a @ b   (f32x2)
__device__ __forceinline__ void mm32(float* __restrict__ out,
                                     const float* __restrict__ a,
                                     const float* __restrict__ b,
                                     const float* __restrict__ adds,
                                     int tid) {
    int i  = tid >> 3;
    int j4 = (tid & 7) << 2;
    float ar[32];
#pragma unroll
    for (int c = 0; c < 8; c++) {
        float4 t = *(const float4*)(a + i * 32 + c * 4);
        ar[c*4+0] = t.x; ar[c*4+1] = t.y; ar[c*4+2] = t.z; ar[c*4+3] = t.w;
    }
    u64 acc01 = 0, acc23 = 0;
    if (adds) {
        ulonglong2 ad = *(const ulonglong2*)(adds + i * 32 + j4);
        acc01 = ad.x; acc23 = ad.y;
    }
#pragma unroll
    for (int kk = 0; kk < 32; kk++) {
        ulonglong2 b2 = *(const ulonglong2*)(b + kk * 32 + j4);
        u64 a2; PK2(a2, ar[kk], ar[kk]);
        FMA2(acc01, a2, b2.x, acc01);
        FMA2(acc23, a2, b2.y, acc23);
    }
    ulonglong2 o; o.x = acc01; o.y = acc23;
    *(ulonglong2*)(out + i * 32 + j4) = o;
}

// ---------------------------------------------------------------------------
// Kernel 1: per chunk-tile (4096 CTAs).
// ---------------------------------------------------------------------------
extern __shared__ float sm1[];

__global__ void __launch_bounds__(256, 3)
k1_kernel(const float* __restrict__ q, const float* __restrict__ k,
          const float* __restrict__ v, const float* __restrict__ beta) {
    float* qn   = sm1;               // 32*PW
    float* kn   = qn + 32 * PW;      // 32*PW
    float* vbkt = kn + 32 * PW;      // 32*PW  (kt first, vb later)
    float* Am = vbkt + 32 * PW;      // 1024
    float* Bm = Am + 1024;
    float* Xm = Bm + 1024;
    float* Ym = Xm + 1024;
    float* beta_s = Ym + 1024;       // 32

    const int tid  = threadIdx.x;
    const int tile = blockIdx.x;
    const size_t base = (size_t)tile * 4096;
    const int brow = tile * 32;

    // ---- load + l2norm q,k ----
    {
        int wp = tid >> 5, lane = tid & 31;
#pragma unroll
        for (int rr = 0; rr < 4; rr++) {
            int r = wp * 4 + rr;
            float4 a = *(const float4*)(q + base + r * 128 + lane * 4);
            float s = a.x*a.x + a.y*a.y + a.z*a.z + a.w*a.w;
#pragma unroll
            for (int off = 16; off; off >>= 1) s += __shfl_xor_sync(0xffffffffu, s, off);
            float sc = rsqrtf(s + 1e-6f);
            float4 o = make_float4(a.x*sc, a.y*sc, a.z*sc, a.w*sc);
            *(float4*)(qn + r * PW + lane * 4) = o;
            *(float4*)(g_qn + base + r * 128 + lane * 4) = o;

            float4 b = *(const float4*)(k + base + r * 128 + lane * 4);
            float sk = b.x*b.x + b.y*b.y + b.z*b.z + b.w*b.w;
#pragma unroll
            for (int off = 16; off; off >>= 1) sk += __shfl_xor_sync(0xffffffffu, sk, off);
            float sck = rsqrtf(sk + 1e-6f);
            float4 ok = make_float4(b.x*sck, b.y*sck, b.z*sck, b.w*sck);
            *(float4*)(kn + r * PW + lane * 4) = ok;
            *(float4*)(g_kn + base + r * 128 + lane * 4) = ok;
        }
        if (tid < 32) beta_s[tid] = beta[brow + tid];
    }
    __syncthreads();

    // ---- build kt (128 x 32, stride 32) into vbkt: kt[c*32+r] = kn[r][c] ----
    {
#pragma unroll
        for (int t = 0; t < 4; t++) {
            int idx = tid + t * 256;        // 0..1023
            int r = idx & 31, g = idx >> 5; // g: float4 group 0..31
            float4 f = *(const float4*)(kn + r * PW + g * 4);
            vbkt[(4*g+0) * 32 + r] = f.x;
            vbkt[(4*g+1) * 32 + r] = f.y;
            vbkt[(4*g+2) * 32 + r] = f.z;
            vbkt[(4*g+3) * 32 + r] = f.w;
        }
    }
    __syncthreads();

    // ---- T0/attn: K-split halves, 2 rows x 4 cols per thread ----
    {
        const float* kt = vbkt;
        const int h  = tid >> 7;
        const int t  = tid & 127;
        const int r0 = (t >> 3) * 2, r1 = r0 + 1;
        const int j4 = (t & 7) << 2;
        u64 aK0a=0,aK0b=0,aK1a=0,aK1b=0, aQ0a=0,aQ0b=0,aQ1a=0,aQ1b=0;
        const int c0 = h * 64;
#pragma unroll 4
        for (int c = c0; c < c0 + 64; c++) {
            ulonglong2 kt2 = *(const ulonglong2*)(kt + c * 32 + j4);
            float k0v = kn[r0*PW + c], k1v = kn[r1*PW + c];
            float q0v = qn[r0*PW + c], q1v = qn[r1*PW + c];
            u64 k02,k12,q02,q12;
            PK2(k02,k0v,k0v); PK2(k12,k1v,k1v); PK2(q02,q0v,q0v); PK2(q12,q1v,q1v);
            FMA2(aK0a,k02,kt2.x,aK0a); FMA2(aK0b,k02,kt2.y,aK0b);
            FMA2(aK1a,k12,kt2.x,aK1a); FMA2(aK1b,k12,kt2.y,aK1b);
            FMA2(aQ0a,q02,kt2.x,aQ0a); FMA2(aQ0b,q02,kt2.y,aQ0b);
            FMA2(aQ1a,q12,kt2.x,aQ1a); FMA2(aQ1b,q12,kt2.y,aQ1b);
        }
        if (h == 1) {
            *(u64*)(Bm + r0*32 + j4)   = aK0a; *(u64*)(Bm + r0*32 + j4+2) = aK0b;
            *(u64*)(Bm + r1*32 + j4)   = aK1a; *(u64*)(Bm + r1*32 + j4+2) = aK1b;
            *(u64*)(Ym + r0*32 + j4)   = aQ0a; *(u64*)(Ym + r0*32 + j4+2) = aQ0b;
            *(u64*)(Ym + r1*32 + j4)   = aQ1a; *(u64*)(Ym + r1*32 + j4+2) = aQ1b;
        }
        __syncthreads();
        if (h == 0) {
            ADD2(aK0a, aK0a, *(const u64*)(Bm + r0*32 + j4));
            ADD2(aK0b, aK0b, *(const u64*)(Bm + r0*32 + j4+2));
            ADD2(aK1a, aK1a, *(const u64*)(Bm + r1*32 + j4));
            ADD2(aK1b, aK1b, *(const u64*)(Bm + r1*32 + j4+2));
            ADD2(aQ0a, aQ0a, *(const u64*)(Ym + r0*32 + j4));
            ADD2(aQ0b, aQ0b, *(const u64*)(Ym + r0*32 + j4+2));
            ADD2(aQ1a, aQ1a, *(const u64*)(Ym + r1*32 + j4));
            ADD2(aQ1b, aQ1b, *(const u64*)(Ym + r1*32 + j4+2));
            float K0[4], K1[4], Q0[4], Q1[4];
            UPK2(K0[0],K0[1],aK0a); UPK2(K0[2],K0[3],aK0b);
            UPK2(K1[0],K1[1],aK1a); UPK2(K1[2],K1[3],aK1b);
            UPK2(Q0[0],Q0[1],aQ0a); UPK2(Q0[2],Q0[3],aQ0b);
            UPK2(Q1[0],Q1[1],aQ1a); UPK2(Q1[2],Q1[3],aQ1b);
#pragma unroll
            for (int rr = 0; rr < 2; rr++) {
                int row = r0 + rr;
                const float* K = rr ? K1 : K0;
                const float* Q = rr ? Q1 : Q0;
                float bb = beta_s[row];
                float att[4];
#pragma unroll
                for (int m = 0; m < 4; m++) {
                    int j = j4 + m;
                    float t0 = (row > j) ? (-bb * K[m]) : 0.f;
                    Am[row*32 + j] = t0;
                    Xm[row*32 + j] = t0 + ((row == j) ? 1.f : 0.f);
                    att[m] = (row >= j) ? Q[m] : 0.f;
                }
                *(float4*)(g_attn + (size_t)tile * 1024 + row * 32 + j4) =
                    make_float4(att[0], att[1], att[2], att[3]);
            }
        }
        __syncthreads();
    }

    // ---- (I - T0)^{-1} via nilpotent squaring ----
    float *Ap = Am, *Bp = Bm, *Xp = Xm, *Yp = Ym;
#pragma unroll 1
    for (int s = 0; s < 4; s++) {
        mm32(Bp, Ap, Ap, nullptr, tid);
        __syncthreads();
        mm32(Yp, Xp, Bp, Xp, tid);
        __syncthreads();
        float* t;
        t = Ap; Ap = Bp; Bp = t;
        t = Xp; Xp = Yp; Yp = t;
    }

    // ---- vb = v * beta (into vbkt; kt is dead) ----
    for (int x = tid; x < 1024; x += 256) {
        int r = x >> 5, c4 = (x & 31) << 2;
        float4 vv = *(const float4*)(v + base + r * 128 + c4);
        float bb = beta_s[r];
        *(float4*)(vbkt + r * PW + c4) = make_float4(vv.x*bb, vv.y*bb, vv.z*bb, vv.w*bb);
    }
    __syncthreads();

    // ---- g_w = -(Xp @ (kn * beta)), g_u = Xp @ vb ----
    {
        int i  = tid >> 3;
        int jg = tid & 7;
        float xr[32], xnb[32];
#pragma unroll
        for (int c = 0; c < 8; c++) {
            float4 t = *(const float4*)(Xp + i * 32 + c * 4);
            xr[c*4+0] = t.x; xr[c*4+1] = t.y; xr[c*4+2] = t.z; xr[c*4+3] = t.w;
        }
#pragma unroll
        for (int kk = 0; kk < 32; kk++) xnb[kk] = -xr[kk] * beta_s[kk];

#pragma unroll 1
        for (int cblk = 0; cblk < 4; cblk++) {
            int c = cblk * 32 + jg * 4;
            u64 w01 = 0, w23 = 0, u01 = 0, u23 = 0;
#pragma unroll
            for (int kk = 0; kk < 32; kk++) {
                ulonglong2 k2v = *(const ulonglong2*)(kn   + kk * PW + c);
                ulonglong2 v2v = *(const ulonglong2*)(vbkt + kk * PW + c);
                u64 xb2, xr2;
                PK2(xb2, xnb[kk], xnb[kk]); PK2(xr2, xr[kk], xr[kk]);
                FMA2(w01, xb2, k2v.x, w01); FMA2(w23, xb2, k2v.y, w23);
                FMA2(u01, xr2, v2v.x, u01); FMA2(u23, xr2, v2v.y, u23);
            }
            ulonglong2 ow; ow.x = w01; ow.y = w23;
            ulonglong2 ou; ou.x = u01; ou.y = u23;
            *(ulonglong2*)(g_w + base + i * 128 + c) = ow;
            *(ulonglong2*)(g_u + base + i * 128 + c) = ou;
        }
    }
}

// ---------------------------------------------------------------------------
// Kernel 2: sequential scan, 512 threads, K-split halves, f32x2, cp.async.
// ---------------------------------------------------------------------------
#define BUF_FLOATS (3 * 32 * PW + 2 * 32 * PS)   // 12672 + 2304 = 14976

extern __shared__ float sm2[];

__device__ __forceinline__ void k2_prefetch(int n, float* buf, int bh, int sl, int tid) {
    const size_t tb = ((size_t)bh * 128 + n) * 4096;
    float* w = buf;
    float* q = buf + 32 * PW;
    float* k = buf + 64 * PW;
    float* u = buf + 96 * PW;
    float* a = buf + 96 * PW + 32 * PS;
#pragma unroll
    for (int t = 0; t < 2; t++) {
        int idx = tid + t * 512;               // 0..1023
        int r = idx >> 5, c4 = (idx & 31) << 2;
        cpa16(w + r * PW + c4, g_w  + tb + r * 128 + c4);
        cpa16(q + r * PW + c4, g_qn + tb + r * 128 + c4);
        cpa16(k + r * PW + c4, g_kn + tb + r * 128 + c4);
    }
    if (tid < 256) {
        int r = tid >> 3, c4 = (tid & 7) << 2;
        cpa16(u + r * PS + c4, g_u + tb + r * 128 + sl * 32 + c4);
    } else {
        int t2 = tid - 256;
        int r = t2 >> 3, c4 = (t2 & 7) << 2;
        cpa16(a + r * PS + c4, g_attn + ((size_t)bh * 128 + n) * 1024 + r * 32 + c4);
    }
}

__global__ void __launch_bounds__(512, 1)
k2_kernel(float* __restrict__ out, int out_size) {
    float* S    = sm2;                        // 128*PS = 4608
    float* uish = S + 128 * PS;               // 32*PS
    float* pA   = uish + 32 * PS;             // 32*PS
    float* pO   = pA + 32 * PS;               // 32*PS
    float* bufs = pO + 32 * PS;               // 2*BUF_FLOATS

    const int tid = threadIdx.x;
    const int sl  = blockIdx.x;
    const int bh  = blockIdx.z * 16 + blockIdx.y;
    const int h   = tid >> 8;
    const int t8  = tid & 255;
    const int i   = t8 >> 3;
    const int j4  = (t8 & 7) << 2;
    const int kb  = h * 64;
    // update-stage mapping
    const int ur0 = (tid >> 4) * 4;
    const int uj2 = (tid & 15) << 1;

    for (int x = tid; x < 128 * PS; x += 512) S[x] = 0.f;

    k2_prefetch(0, bufs, bh, sl, tid);
    CP_COMMIT();

#pragma unroll 1
    for (int n = 0; n < 128; n++) {
        float* buf = bufs + (n & 1) * BUF_FLOATS;
        CP_WAIT0();
        __syncthreads();                                   // A
        if (n + 1 < 128) { k2_prefetch(n + 1, bufs + ((n + 1) & 1) * BUF_FLOATS, bh, sl, tid); CP_COMMIT(); }

        const float* w = buf;
        const float* q = buf + 32 * PW;
        const float* k = buf + 64 * PW;
        const float* u = buf + 96 * PW;
        const float* a = buf + 96 * PW + 32 * PS;

        // main: aui = [h0: u0] + (-w)@S_half ; ao = q@S_half   (f32x2)
        u64 aui01 = 0, aui23 = 0, ao01 = 0, ao23 = 0;
        if (h == 0) {
            ulonglong2 t = *(const ulonglong2*)(u + i * PS + j4);
            aui01 = t.x; aui23 = t.y;
        }
#pragma unroll 2
        for (int kk4 = 0; kk4 < 16; kk4++) {
            float4 w4 = *(const float4*)(w + i * PW + kb + kk4 * 4);
            float4 q4 = *(const float4*)(q + i * PW + kb + kk4 * 4);
#define MSTEP(m, wc, qc)                                                        \
            {                                                                   \
                ulonglong2 s2 = *(const ulonglong2*)(S + (kb + kk4*4 + m) * PS + j4); \
                u64 w2, q2; PK2(w2, wc, wc); PK2(q2, qc, qc);                   \
                FMA2(aui01, w2, s2.x, aui01); FMA2(aui23, w2, s2.y, aui23);     \
                FMA2(ao01,  q2, s2.x, ao01);  FMA2(ao23,  q2, s2.y, ao23);      \
            }
            MSTEP(0, w4.x, q4.x) MSTEP(1, w4.y, q4.y)
            MSTEP(2, w4.z, q4.z) MSTEP(3, w4.w, q4.w)
#undef MSTEP
        }
        if (h == 1) {
            *(u64*)(pA + i * PS + j4)     = aui01;
            *(u64*)(pA + i * PS + j4 + 2) = aui23;
            *(u64*)(pO + i * PS + j4)     = ao01;
            *(u64*)(pO + i * PS + j4 + 2) = ao23;
        }
        __syncthreads();                                   // B
        if (h == 0) {
            ADD2(aui01, aui01, *(const u64*)(pA + i * PS + j4));
            ADD2(aui23, aui23, *(const u64*)(pA + i * PS + j4 + 2));
            ADD2(ao01,  ao01,  *(const u64*)(pO + i * PS + j4));
            ADD2(ao23,  ao23,  *(const u64*)(pO + i * PS + j4 + 2));
            *(u64*)(uish + i * PS + j4)     = aui01;
            *(u64*)(uish + i * PS + j4 + 2) = aui23;
        }
        __syncthreads();                                   // C
        if (h == 0) {
            // o = ao + attn @ ui
#pragma unroll
            for (int c4 = 0; c4 < 8; c4++) {
                float4 a4 = *(const float4*)(a + i * PS + c4 * 4);
#define ASTEP(m, ac)                                                            \
                {                                                               \
                    ulonglong2 uu = *(const ulonglong2*)(uish + (c4*4 + m) * PS + j4); \
                    u64 a2; PK2(a2, ac, ac);                                    \
                    FMA2(ao01, a2, uu.x, ao01); FMA2(ao23, a2, uu.y, ao23);     \
                }
                ASTEP(0, a4.x) ASTEP(1, a4.y) ASTEP(2, a4.z) ASTEP(3, a4.w)
#undef ASTEP
            }
            ulonglong2 ov; ov.x = ao01; ov.y = ao23;
            *(ulonglong2*)(out + ((size_t)bh * 4096 + n * 32 + i) * 128 + sl * 32 + j4) = ov;
        }

        // S += kn^T @ ui  (all 512 threads; 4 contig rows x 2 cols each)
        {
            u64 s0 = *(const u64*)(S + (ur0 + 0) * PS + uj2);
            u64 s1 = *(const u64*)(S + (ur0 + 1) * PS + uj2);
            u64 s2v = *(const u64*)(S + (ur0 + 2) * PS + uj2);
            u64 s3 = *(const u64*)(S + (ur0 + 3) * PS + uj2);
#pragma unroll 4
            for (int c = 0; c < 32; c++) {
                float4 k4 = *(const float4*)(k + c * PW + ur0);
                u64 uu = *(const u64*)(uish + c * PS + uj2);
                u64 k02, k12, k22, k32;
                PK2(k02, k4.x, k4.x); PK2(k12, k4.y, k4.y);
                PK2(k22, k4.z, k4.z); PK2(k32, k4.w, k4.w);
                FMA2(s0, k02, uu, s0);
                FMA2(s1, k12, uu, s1);
                FMA2(s2v, k22, uu, s2v);
                FMA2(s3, k32, uu, s3);
            }
            *(u64*)(S + (ur0 + 0) * PS + uj2) = s0;
            *(u64*)(S + (ur0 + 1) * PS + uj2) = s1;
            *(u64*)(S + (ur0 + 2) * PS + uj2) = s2v;
            *(u64*)(S + (ur0 + 3) * PS + uj2) = s3;
        }
    }
    __syncthreads();

    // final state S -> second output tensor (b,h,dk,dv)
    if (out_size >= OUT_ELEMS + S_ELEMS) {
        int ii = tid >> 3;                  // 0..63
        int jj4 = (tid & 7) << 2;
#pragma unroll
        for (int rb = 0; rb < 2; rb++) {
            int kd = ii + rb * 64;
            *(ulonglong2*)(out + OUT_ELEMS + ((size_t)bh * 128 + kd) * 128 + sl * 32 + jj4) =
                *(const ulonglong2*)(S + kd * PS + jj4);
        }
    }
}

// ---------------------------------------------------------------------------
extern "C" void kernel_launch(void* const* d_in, const int* in_sizes, int n_in,
                              void* d_out, int out_size) {
    const float* q    = (const float*)d_in[0];
    const float* k    = (const float*)d_in[1];
    const float* v    = (const float*)d_in[2];
    const float* beta = (const float*)d_in[3];
    float* out = (float*)d_out;

    const int k1_smem = (3 * 32 * PW + 4 * 1024 + 32) * 4;                     // 67,328 B
    const int k2_smem = (128 * PS + 3 * 32 * PS + 2 * BUF_FLOATS) * 4;         // 152,064 B

    cudaFuncSetAttribute(k1_kernel, cudaFuncAttributeMaxDynamicSharedMemorySize, k1_smem);
    cudaFuncSetAttribute(k2_kernel, cudaFuncAttributeMaxDynamicSharedMemorySize, k2_smem);

    k1_kernel<<<NTILES, 256, k1_smem>>>(q, k, v, beta);
    k2_kernel<<<dim3(4, 16, 2), 512, k2_smem>>>(out, out_size);
}